// round 15
// baseline (speedup 1.0000x reference)
#include <cuda_runtime.h>
#include <cstdint>

// out[b,c,h,w] = (1/256) * sum_{p,o in 0..8} inp[b, p*9+o, h, w] * sec[b, c, h+p-4, w+o-4]
// mma.sync m16n8k8 tf32. CTA = 32ch x 16px x all h, NT=128, 4 CTAs/SM.
// R13 + hoisted h-invariant staging math (R14) with the aptr sign bug fixed:
// px is used SIGNED in the pointer (masked loads never deref out-of-range).

#define HH 128
#define WW 128
#define CC 256
#define MD 4
#define HW (HH*WW)

#define NT 128
#define MCH 32
#define RSLOT (2*3*512)          // 3072
#define RING_BYTES (10*RSLOT)    // 30720
#define B_OFF RING_BYTES
#define BBYTES (9*2*512)         // 9216
#define SMEM_BYTES (B_OFF + 2*BBYTES)   // 49152

static __device__ __forceinline__ uint32_t f2tf(float f) {
    uint32_t r; asm("cvt.rna.tf32.f32 %0, %1;" : "=r"(r) : "f"(f)); return r;
}

static __device__ __forceinline__ void mma8(float* d, const uint4& a, uint32_t b0, uint32_t b1) {
    asm volatile("mma.sync.aligned.m16n8k8.row.col.f32.tf32.tf32.f32 "
                 "{%0,%1,%2,%3}, {%4,%5,%6,%7}, {%8,%9}, {%0,%1,%2,%3};"
                 : "+f"(d[0]), "+f"(d[1]), "+f"(d[2]), "+f"(d[3])
                 : "r"(a.x), "r"(a.y), "r"(a.z), "r"(a.w), "r"(b0), "r"(b1));
}

__global__ void __launch_bounds__(NT, 4)
corr_mma_kernel(const float* __restrict__ inp,
                const float* __restrict__ sec,
                float* __restrict__ out)
{
    extern __shared__ char smem[];
    const int tid  = threadIdx.x;
    const int wid  = tid >> 5;
    const int lane = tid & 31;
    const int w0   = blockIdx.x * 16;
    const int c0   = blockIdx.y * MCH;
    const int b    = blockIdx.z;

    const int cbw = wid & 1;      // warp's channel block (16 ch)
    const int ntw = wid >> 1;     // warp's n-tile (8 px)

    // ================= hoisted stA/ldA descriptors (2 slots) =================
    bool aact[2], am0[2], am1[2];
    const float* aptr[2];
    int asmo[2];
    #pragma unroll
    for (int i = 0; i < 2; i++) {
        int idx = tid + i * NT;
        aact[i] = idx < 192;
        int l  = idx & 31;
        int s  = (idx >> 5) % 3;
        int cb = idx / 96;
        int ch = (cb & 1) * 16 + (l >> 2);
        int px = w0 - 4 + s * 8 + (l & 3);
        am0[i] = aact[i] && ((unsigned)px < WW);
        am1[i] = aact[i] && ((unsigned)(px + 4) < WW);
        aptr[i] = sec + ((size_t)(b * CC + c0 + ch) * HH) * WW + px;   // px SIGNED
        asmo[i] = ((cb & 1) * 3 + s) * 512 + l * 16;
    }

    // ================= hoisted ldB/stB descriptors (5 slots) =================
    bool bact[5], bm0[5], bm1[5], bm2[5], bm3[5];
    const float* bptr[5];
    int bsmo[5];
    #pragma unroll
    for (int i = 0; i < 5; i++) {
        int idx = tid + i * NT;
        bact[i] = idx < 576;
        int l  = idx & 31;
        int nt = (idx >> 5) & 1;
        int p  = (idx >> 6) < 9 ? (idx >> 6) : 8;
        int x  = 8 * nt + (l >> 2);
        int o0 = (l & 3) - (l >> 2);
        bm0[i] = bact[i] && ((unsigned)(o0)      <= 8u);
        bm1[i] = bact[i] && ((unsigned)(o0 + 4)  <= 8u);
        bm2[i] = bact[i] && ((unsigned)(o0 + 8)  <= 8u);
        bm3[i] = bact[i] && ((unsigned)(o0 + 12) <= 8u);
        bptr[i] = inp + ((size_t)(b * 81 + p * 9) * HH) * WW
                      + (w0 + x) + (ptrdiff_t)o0 * HW;
        bsmo[i] = (idx < 576 ? idx : 0) * 16;
    }

    float4 pA[2], pB[5];

    auto ldA = [&](int r) {
        #pragma unroll
        for (int i = 0; i < 2; i++) {
            const float* q = aptr[i] + (r << 7);
            float f0 = am0[i] ? __ldg(q)              : 0.f;
            float f1 = am0[i] ? __ldg(q + 8 * HW)     : 0.f;
            float f2 = am1[i] ? __ldg(q + 4)          : 0.f;
            float f3 = am1[i] ? __ldg(q + 8 * HW + 4) : 0.f;
            pA[i] = make_float4(f0, f1, f2, f3);
        }
    };
    auto stA = [&](int slot) {
        #pragma unroll
        for (int i = 0; i < 2; i++) {
            if (aact[i]) {
                uint4 v = make_uint4(f2tf(pA[i].x), f2tf(pA[i].y), f2tf(pA[i].z), f2tf(pA[i].w));
                *(uint4*)(smem + slot * RSLOT + asmo[i]) = v;
            }
        }
    };
    auto ldB = [&](int hb) {
        #pragma unroll
        for (int i = 0; i < 5; i++) {
            const float* q = bptr[i] + (hb << 7);
            float g0 = bm0[i] ? __ldg(q)           : 0.f;
            float g1 = bm1[i] ? __ldg(q + 4 * HW)  : 0.f;
            float g2 = bm2[i] ? __ldg(q + 8 * HW)  : 0.f;
            float g3 = bm3[i] ? __ldg(q + 12 * HW) : 0.f;
            pB[i] = make_float4(g0, g1, g2, g3);
        }
    };
    auto stB = [&](int bufsel) {
        #pragma unroll
        for (int i = 0; i < 5; i++) {
            if (bact[i]) {
                uint4 v = make_uint4(f2tf(pB[i].x), f2tf(pB[i].y), f2tf(pB[i].z), f2tf(pB[i].w));
                *(uint4*)(smem + B_OFF + bufsel * BBYTES + bsmo[i]) = v;
            }
        }
    };

    // ================= prologue =================
    for (int r = 0; r < 5; r++) { ldA(r); stA(r); }
    ldB(0); stB(0);
    ldA(5);
    ldB(1);
    __syncthreads();

    const unsigned aoff_warp = (unsigned)(cbw * 3 * 512 + lane * 16);
    const unsigned boff_lane = (unsigned)(ntw * 512 + lane * 16);
    const float sc = 1.0f / (float)CC;

    int slot_st = 5;          // ring slot receiving row h+5
    int s0 = 6;               // ring slot of row h-4 (h=0): (0-4) mod 10
    float* ob = out + ((size_t)(b * CC + c0 + cbw * 16 + (lane >> 2)) * HH) * WW
                    + w0 + ntw * 8 + 2 * (lane & 3);

    #pragma unroll 1
    for (int h = 0; h < HH; h++) {
        const int buf = h & 1;

        // step 1: publish pending staging
        if (h + 5 < HH) { stA(slot_st); slot_st = (slot_st == 9) ? 0 : slot_st + 1; }
        if (h + 1 < HH) stB(buf ^ 1);

        // step 2: prefetch next pending
        if (h + 6 < HH) ldA(h + 6);
        if (h + 2 < HH) ldB(h + 2);

        // step 3: compute
        float accE[4] = {0.f, 0.f, 0.f, 0.f};
        float accO[4] = {0.f, 0.f, 0.f, 0.f};
        const char* bbase = smem + B_OFF + buf * BBYTES;
        if (h >= MD && h < HH - MD) {
            int sl = s0;
            #pragma unroll
            for (int p = 0; p < 9; p++) {
                const char* ab = smem + sl * RSLOT + aoff_warp;
                uint4 A0 = *(const uint4*)(ab + ntw * 512);
                uint4 A1 = *(const uint4*)(ab + (ntw + 1) * 512);
                uint4 B0 = *(const uint4*)(bbase + p * 1024 + boff_lane);
                float* acc = (p & 1) ? accO : accE;
                mma8(acc, A0, B0.x, B0.y);
                mma8(acc, A1, B0.z, B0.w);
                sl = (sl == 9) ? 0 : sl + 1;
            }
        } else {
            int sl = s0;
            #pragma unroll
            for (int p = 0; p < 9; p++) {
                int r = h + p - MD;
                if ((unsigned)r < (unsigned)HH) {
                    const char* ab = smem + sl * RSLOT + aoff_warp;
                    uint4 A0 = *(const uint4*)(ab + ntw * 512);
                    uint4 A1 = *(const uint4*)(ab + (ntw + 1) * 512);
                    uint4 B0 = *(const uint4*)(bbase + p * 1024 + boff_lane);
                    float* acc = (p & 1) ? accO : accE;
                    mma8(acc, A0, B0.x, B0.y);
                    mma8(acc, A1, B0.z, B0.w);
                }
                sl = (sl == 9) ? 0 : sl + 1;
            }
        }
        s0 = (s0 == 9) ? 0 : s0 + 1;

        // step 4: epilogue
        *(float2*)(ob)          = make_float2((accE[0] + accO[0]) * sc, (accE[1] + accO[1]) * sc);
        *(float2*)(ob + 8 * HW) = make_float2((accE[2] + accO[2]) * sc, (accE[3] + accO[3]) * sc);
        ob += WW;

        // step 5: barrier
        __syncthreads();
    }
}

extern "C" void kernel_launch(void* const* d_in, const int* in_sizes, int n_in,
                              void* d_out, int out_size)
{
    const float* inp = (const float*)d_in[0];   // [B, 81, 128, 128]
    const float* sec = (const float*)d_in[1];   // [B, 256, 128, 128]
    float* out = (float*)d_out;                 // [B, 256, 128, 128]

    const int B = in_sizes[0] / (81 * HH * WW);

    cudaFuncSetAttribute(corr_mma_kernel,
                         cudaFuncAttributeMaxDynamicSharedMemorySize, SMEM_BYTES);

    dim3 grid(WW / 16, CC / MCH, B);   // (8, 8, 8) = 512 CTAs
    corr_mma_kernel<<<grid, NT, SMEM_BYTES>>>(inp, sec, out);
}

// round 16
// speedup vs baseline: 1.2069x; 1.2069x over previous
#include <cuda_runtime.h>
#include <cstdint>

// out[b,c,h,w] = (1/256) * sum_{p,o in 0..8} inp[b, p*9+o, h, w] * sec[b, c, h+p-4, w+o-4]
// mma.sync m16n8k8 tf32. Two kernels:
//   1) prep: build banded-B fragments once per (b,wtile,h) into __device__ scratch
//   2) main: CTA = 32ch x 16px x all h; B staged via coalesced LDG.128 from scratch.

#define HH 128
#define WW 128
#define CC 256
#define MD 4
#define HW (HH*WW)

#define NT 128
#define MCH 32
#define NFRAG 576                 // 9p x 2nt x 32 lanes
#define RSLOT (2*3*512)           // 3072
#define RING_BYTES (10*RSLOT)     // 30720
#define B_OFF RING_BYTES
#define BBYTES (NFRAG*16)         // 9216
#define SMEM_BYTES (B_OFF + 2*BBYTES)   // 49152

__device__ uint4 g_bfrag[(size_t)8 * 8 * 128 * NFRAG];   // [b][wt][h][idx] 75.5MB

static __device__ __forceinline__ uint32_t f2tf(float f) {
    uint32_t r; asm("cvt.rna.tf32.f32 %0, %1;" : "=r"(r) : "f"(f)); return r;
}

static __device__ __forceinline__ void mma8(float* d, const uint4& a, uint32_t b0, uint32_t b1) {
    asm volatile("mma.sync.aligned.m16n8k8.row.col.f32.tf32.tf32.f32 "
                 "{%0,%1,%2,%3}, {%4,%5,%6,%7}, {%8,%9}, {%0,%1,%2,%3};"
                 : "+f"(d[0]), "+f"(d[1]), "+f"(d[2]), "+f"(d[3])
                 : "r"(a.x), "r"(a.y), "r"(a.z), "r"(a.w), "r"(b0), "r"(b1));
}

// ---- prep: one thread = one B fragment (p, nt, lane) for one (b, wt, h) ----
__global__ void __launch_bounds__(NFRAG)
prep_b_kernel(const float* __restrict__ inp)
{
    const int idx = threadIdx.x;          // 0..575
    const int wt  = blockIdx.x;
    const int h   = blockIdx.y;
    const int b   = blockIdx.z;
    const int w0  = wt * 16;

    const int l  = idx & 31;
    const int nt = (idx >> 5) & 1;
    const int p  = idx >> 6;
    const int x  = 8 * nt + (l >> 2);
    const int o0 = (l & 3) - (l >> 2);

    const float* ib = inp + ((size_t)(b * 81 + p * 9) * HH + h) * WW + (w0 + x)
                          + (ptrdiff_t)o0 * HW;
    float g0 = ((unsigned)(o0)      <= 8u) ? __ldg(ib)           : 0.f;
    float g1 = ((unsigned)(o0 + 4)  <= 8u) ? __ldg(ib + 4 * HW)  : 0.f;
    float g2 = ((unsigned)(o0 + 8)  <= 8u) ? __ldg(ib + 8 * HW)  : 0.f;
    float g3 = ((unsigned)(o0 + 12) <= 8u) ? __ldg(ib + 12 * HW) : 0.f;

    g_bfrag[(((size_t)b * 8 + wt) * 128 + h) * NFRAG + idx] =
        make_uint4(f2tf(g0), f2tf(g1), f2tf(g2), f2tf(g3));
}

__global__ void __launch_bounds__(NT, 4)
corr_mma_kernel(const float* __restrict__ inp,
                const float* __restrict__ sec,
                float* __restrict__ out)
{
    extern __shared__ char smem[];
    const int tid  = threadIdx.x;
    const int wid  = tid >> 5;
    const int lane = tid & 31;
    const int w0   = blockIdx.x * 16;
    const int c0   = blockIdx.y * MCH;
    const int b    = blockIdx.z;

    const int cbw = wid & 1;      // warp's channel block (16 ch)
    const int ntw = wid >> 1;     // warp's n-tile (8 px)

    // ---- hoisted ldA/stA descriptors (2 slots) ----
    bool aact[2], am0[2], am1[2];
    const float* aptr[2];
    int asmo[2];
    #pragma unroll
    for (int i = 0; i < 2; i++) {
        int idx = tid + i * NT;
        aact[i] = idx < 192;
        int l  = idx & 31;
        int s  = (idx >> 5) % 3;
        int cb = (idx / 96) & 1;
        int ch = cb * 16 + (l >> 2);
        int px = w0 - 4 + s * 8 + (l & 3);
        am0[i] = aact[i] && ((unsigned)px < WW);
        am1[i] = aact[i] && ((unsigned)(px + 4) < WW);
        aptr[i] = sec + ((size_t)(b * CC + c0 + ch) * HH) * WW + px;   // px signed
        asmo[i] = (cb * 3 + s) * 512 + l * 16;
    }

    const uint4* bsrc = g_bfrag + (((size_t)b * 8 + blockIdx.x) * 128) * NFRAG;

    float4 pA[2];
    uint4  pB[5];

    auto ldA = [&](int r) {
        #pragma unroll
        for (int i = 0; i < 2; i++) {
            const float* q = aptr[i] + (r << 7);
            float f0 = am0[i] ? __ldg(q)              : 0.f;
            float f1 = am0[i] ? __ldg(q + 8 * HW)     : 0.f;
            float f2 = am1[i] ? __ldg(q + 4)          : 0.f;
            float f3 = am1[i] ? __ldg(q + 8 * HW + 4) : 0.f;
            pA[i] = make_float4(f0, f1, f2, f3);
        }
    };
    auto stA = [&](int slot) {
        #pragma unroll
        for (int i = 0; i < 2; i++) {
            if (aact[i]) {
                uint4 v = make_uint4(f2tf(pA[i].x), f2tf(pA[i].y), f2tf(pA[i].z), f2tf(pA[i].w));
                *(uint4*)(smem + slot * RSLOT + asmo[i]) = v;
            }
        }
    };
    auto ldB = [&](int hb) {
        const uint4* src = bsrc + (size_t)hb * NFRAG;
        #pragma unroll
        for (int i = 0; i < 5; i++) {
            int idx = tid + i * NT;
            if (idx < NFRAG) pB[i] = __ldg(src + idx);
        }
    };
    auto stB = [&](int bufsel) {
        #pragma unroll
        for (int i = 0; i < 5; i++) {
            int idx = tid + i * NT;
            if (idx < NFRAG)
                *(uint4*)(smem + B_OFF + bufsel * BBYTES + idx * 16) = pB[i];
        }
    };

    // ---- prologue ----
    for (int r = 0; r < 5; r++) { ldA(r); stA(r); }
    ldB(0); stB(0);
    ldA(5);
    ldB(1);
    __syncthreads();

    const unsigned aoff_warp = (unsigned)(cbw * 3 * 512 + lane * 16);
    const unsigned boff_lane = (unsigned)(ntw * 512 + lane * 16);
    const float sc = 1.0f / (float)CC;

    int slot_st = 5;
    int s0 = 6;
    float* ob = out + ((size_t)(b * CC + c0 + cbw * 16 + (lane >> 2)) * HH) * WW
                    + w0 + ntw * 8 + 2 * (lane & 3);

    #pragma unroll 1
    for (int h = 0; h < HH; h++) {
        const int buf = h & 1;

        // step 1: publish pending staging
        if (h + 5 < HH) { stA(slot_st); slot_st = (slot_st == 9) ? 0 : slot_st + 1; }
        if (h + 1 < HH) stB(buf ^ 1);

        // step 2: prefetch next pending
        if (h + 6 < HH) ldA(h + 6);
        if (h + 2 < HH) ldB(h + 2);

        // step 3: compute
        float accE[4] = {0.f, 0.f, 0.f, 0.f};
        float accO[4] = {0.f, 0.f, 0.f, 0.f};
        const char* bbase = smem + B_OFF + buf * BBYTES;
        if (h >= MD && h < HH - MD) {
            int sl = s0;
            #pragma unroll
            for (int p = 0; p < 9; p++) {
                const char* ab = smem + sl * RSLOT + aoff_warp;
                uint4 A0 = *(const uint4*)(ab + ntw * 512);
                uint4 A1 = *(const uint4*)(ab + (ntw + 1) * 512);
                uint4 B0 = *(const uint4*)(bbase + p * 1024 + boff_lane);
                float* acc = (p & 1) ? accO : accE;
                mma8(acc, A0, B0.x, B0.y);
                mma8(acc, A1, B0.z, B0.w);
                sl = (sl == 9) ? 0 : sl + 1;
            }
        } else {
            int sl = s0;
            #pragma unroll
            for (int p = 0; p < 9; p++) {
                int r = h + p - MD;
                if ((unsigned)r < (unsigned)HH) {
                    const char* ab = smem + sl * RSLOT + aoff_warp;
                    uint4 A0 = *(const uint4*)(ab + ntw * 512);
                    uint4 A1 = *(const uint4*)(ab + (ntw + 1) * 512);
                    uint4 B0 = *(const uint4*)(bbase + p * 1024 + boff_lane);
                    float* acc = (p & 1) ? accO : accE;
                    mma8(acc, A0, B0.x, B0.y);
                    mma8(acc, A1, B0.z, B0.w);
                }
                sl = (sl == 9) ? 0 : sl + 1;
            }
        }
        s0 = (s0 == 9) ? 0 : s0 + 1;

        // step 4: epilogue
        *(float2*)(ob)          = make_float2((accE[0] + accO[0]) * sc, (accE[1] + accO[1]) * sc);
        *(float2*)(ob + 8 * HW) = make_float2((accE[2] + accO[2]) * sc, (accE[3] + accO[3]) * sc);
        ob += WW;

        // step 5: barrier
        __syncthreads();
    }
}

extern "C" void kernel_launch(void* const* d_in, const int* in_sizes, int n_in,
                              void* d_out, int out_size)
{
    const float* inp = (const float*)d_in[0];   // [B, 81, 128, 128]
    const float* sec = (const float*)d_in[1];   // [B, 256, 128, 128]
    float* out = (float*)d_out;                 // [B, 256, 128, 128]

    const int B = in_sizes[0] / (81 * HH * WW);

    cudaFuncSetAttribute(corr_mma_kernel,
                         cudaFuncAttributeMaxDynamicSharedMemorySize, SMEM_BYTES);

    dim3 pgrid(WW / 16, HH, B);                 // (8, 128, 8)
    prep_b_kernel<<<pgrid, NFRAG>>>(inp);

    dim3 grid(WW / 16, CC / MCH, B);            // (8, 8, 8) = 512 CTAs
    corr_mma_kernel<<<grid, NT, SMEM_BYTES>>>(inp, sec, out);
}